// round 1
// baseline (speedup 1.0000x reference)
#include <cuda_runtime.h>

#define DM 64
#define NH 4
#define HD 16
#define BB 16
#define TT 1024
#define ROWS_TOTAL (BB*TT)

// Scratch (device globals: allocation-free per harness rules)
__device__ float g_K[ROWS_TOTAL*DM];    // [b,h,t,16]
__device__ float g_V[ROWS_TOTAL*DM];    // [b,h,t,16]
__device__ float g_Q[ROWS_TOTAL*DM];    // [b,h,t,16]
__device__ float g_ctx[ROWS_TOTAL*DM];  // [b,t,64]

// ---------------------------------------------------------------------------
// KV projection: kv = enc @ Wkv + bkv ; split into K (cols 0..63), V (64..127)
// 256 threads, 64 rows/block. Each thread: 1 column x 32 rows.
// ---------------------------------------------------------------------------
__global__ void __launch_bounds__(256) kv_kernel(const float* __restrict__ enc,
                                                 const float* __restrict__ Wkv,
                                                 const float* __restrict__ bkv) {
    __shared__ float Xs[64][64];    // 16 KB
    __shared__ float Ws[64][128];   // 32 KB
    int rowbase = blockIdx.x * 64;

    for (int i = threadIdx.x; i < 64*128/4; i += 256)
        ((float4*)Ws)[i] = ((const float4*)Wkv)[i];
    for (int i = threadIdx.x; i < 64*64/4; i += 256)
        ((float4*)Xs)[i] = ((const float4*)enc)[rowbase*16 + i];
    __syncthreads();

    int c  = threadIdx.x & 127;
    int rg = threadIdx.x >> 7;   // 0 or 1
    float bias = bkv[c];
    float acc[32];
#pragma unroll
    for (int r = 0; r < 32; r++) acc[r] = bias;

    for (int k = 0; k < 64; k++) {
        float w = Ws[k][c];
#pragma unroll
        for (int r = 0; r < 32; r++) acc[r] += Xs[rg*32 + r][k] * w;
    }

    int h = (c >> 4) & 3;
    int d = c & 15;
    float* dst = (c < 64) ? g_K : g_V;
#pragma unroll
    for (int r = 0; r < 32; r++) {
        int row = rowbase + rg*32 + r;
        int b = row >> 10, t = row & 1023;
        dst[(((b << 2) | h) * 1024 + t) * 16 + d] = acc[r];
    }
}

// ---------------------------------------------------------------------------
// Q projection: q = x @ Wq + bq -> [b,h,t,16]
// 256 threads, 64 rows/block. Each thread: 1 column x 16 rows.
// ---------------------------------------------------------------------------
__global__ void __launch_bounds__(256) q_kernel(const float* __restrict__ x,
                                                const float* __restrict__ Wq,
                                                const float* __restrict__ bq) {
    __shared__ float Xs[64][64];
    __shared__ float Ws[64][64];
    int rowbase = blockIdx.x * 64;

    for (int i = threadIdx.x; i < 64*64/4; i += 256) {
        ((float4*)Ws)[i] = ((const float4*)Wq)[i];
        ((float4*)Xs)[i] = ((const float4*)x)[rowbase*16 + i];
    }
    __syncthreads();

    int c  = threadIdx.x & 63;
    int rg = threadIdx.x >> 6;   // 0..3
    float bias = bq[c];
    float acc[16];
#pragma unroll
    for (int r = 0; r < 16; r++) acc[r] = bias;

    for (int k = 0; k < 64; k++) {
        float w = Ws[k][c];
#pragma unroll
        for (int r = 0; r < 16; r++) acc[r] += Xs[rg*16 + r][k] * w;
    }

    int h = c >> 4;
    int d = c & 15;
#pragma unroll
    for (int r = 0; r < 16; r++) {
        int row = rowbase + rg*16 + r;
        int b = row >> 10, t = row & 1023;
        g_Q[(((b << 2) | h) * 1024 + t) * 16 + d] = acc[r];
    }
}

// ---------------------------------------------------------------------------
// Attention: grid (64 bh, 8 q-tiles), 128 threads, 1 thread = 1 q row.
// K/V tiles of 128 keys in smem; chunk-of-16 online softmax.
// ---------------------------------------------------------------------------
__global__ void __launch_bounds__(128, 4) attn_kernel(const int* __restrict__ mask) {
    __shared__ float Ks[128][16];
    __shared__ float Vs[128][16];
    __shared__ float mb[128];

    int bh = blockIdx.x;           // b*4 + h
    int b  = bh >> 2;
    int h  = bh & 3;
    int t  = blockIdx.y * 128 + threadIdx.x;

    const float4* qp = (const float4*)(g_Q + (bh * 1024 + t) * 16);
    float4 q0 = qp[0], q1 = qp[1], q2 = qp[2], q3 = qp[3];
    float q[16] = {q0.x,q0.y,q0.z,q0.w, q1.x,q1.y,q1.z,q1.w,
                   q2.x,q2.y,q2.z,q2.w, q3.x,q3.y,q3.z,q3.w};

    float m = -1e30f, l = 0.0f;
    float acc[16];
#pragma unroll
    for (int d = 0; d < 16; d++) acc[d] = 0.0f;

    for (int tile = 0; tile < 8; ++tile) {
        int krow = tile * 128 + threadIdx.x;
        const float4* kp = (const float4*)(g_K + (bh * 1024 + krow) * 16);
        const float4* vp = (const float4*)(g_V + (bh * 1024 + krow) * 16);
        float4* ksd = (float4*)Ks[threadIdx.x];
        float4* vsd = (float4*)Vs[threadIdx.x];
        ksd[0] = kp[0]; ksd[1] = kp[1]; ksd[2] = kp[2]; ksd[3] = kp[3];
        vsd[0] = vp[0]; vsd[1] = vp[1]; vsd[2] = vp[2]; vsd[3] = vp[3];
        mb[threadIdx.x] = mask[b * 1024 + krow] ? 0.0f : -1e30f;
        __syncthreads();

#pragma unroll 1
        for (int c0 = 0; c0 < 128; c0 += 16) {
            float s[16];
#pragma unroll
            for (int i = 0; i < 16; i++) {
                const float4* kr = (const float4*)Ks[c0 + i];
                float4 k0 = kr[0], k1 = kr[1], k2 = kr[2], k3 = kr[3];
                float sa = q[0]*k0.x + q[1]*k0.y + q[2]*k0.z + q[3]*k0.w;
                float sb = q[4]*k1.x + q[5]*k1.y + q[6]*k1.z + q[7]*k1.w;
                float sc = q[8]*k2.x + q[9]*k2.y + q[10]*k2.z + q[11]*k2.w;
                float sd = q[12]*k3.x + q[13]*k3.y + q[14]*k3.z + q[15]*k3.w;
                s[i] = ((sa + sb) + (sc + sd)) * 0.25f + mb[c0 + i];
            }
            float cmax = s[0];
#pragma unroll
            for (int i = 1; i < 16; i++) cmax = fmaxf(cmax, s[i]);
            float mnew = fmaxf(m, cmax);
            float f = __expf(m - mnew);
            l *= f;
#pragma unroll
            for (int d = 0; d < 16; d++) acc[d] *= f;
#pragma unroll
            for (int i = 0; i < 16; i++) {
                float p = __expf(s[i] - mnew);
                l += p;
                const float4* vr = (const float4*)Vs[c0 + i];
                float4 v0 = vr[0], v1 = vr[1], v2 = vr[2], v3 = vr[3];
                acc[0]  += p * v0.x; acc[1]  += p * v0.y; acc[2]  += p * v0.z; acc[3]  += p * v0.w;
                acc[4]  += p * v1.x; acc[5]  += p * v1.y; acc[6]  += p * v1.z; acc[7]  += p * v1.w;
                acc[8]  += p * v2.x; acc[9]  += p * v2.y; acc[10] += p * v2.z; acc[11] += p * v2.w;
                acc[12] += p * v3.x; acc[13] += p * v3.y; acc[14] += p * v3.z; acc[15] += p * v3.w;
            }
            m = mnew;
        }
        __syncthreads();
    }

    float inv = 1.0f / l;
    float* op = g_ctx + (b * 1024 + t) * 64 + h * 16;
    float4* o4 = (float4*)op;
    o4[0] = make_float4(acc[0]*inv,  acc[1]*inv,  acc[2]*inv,  acc[3]*inv);
    o4[1] = make_float4(acc[4]*inv,  acc[5]*inv,  acc[6]*inv,  acc[7]*inv);
    o4[2] = make_float4(acc[8]*inv,  acc[9]*inv,  acc[10]*inv, acc[11]*inv);
    o4[3] = make_float4(acc[12]*inv, acc[13]*inv, acc[14]*inv, acc[15]*inv);
}

// ---------------------------------------------------------------------------
// Output projection: out = ctx @ Wproj + bproj
// ---------------------------------------------------------------------------
__global__ void __launch_bounds__(256) proj_kernel(const float* __restrict__ Wp,
                                                   const float* __restrict__ bp,
                                                   float* __restrict__ out) {
    __shared__ float Xs[64][64];
    __shared__ float Ws[64][64];
    int rowbase = blockIdx.x * 64;

    for (int i = threadIdx.x; i < 64*64/4; i += 256) {
        ((float4*)Ws)[i] = ((const float4*)Wp)[i];
        ((float4*)Xs)[i] = ((const float4*)g_ctx)[rowbase*16 + i];
    }
    __syncthreads();

    int c  = threadIdx.x & 63;
    int rg = threadIdx.x >> 6;
    float bias = bp[c];
    float acc[16];
#pragma unroll
    for (int r = 0; r < 16; r++) acc[r] = bias;

    for (int k = 0; k < 64; k++) {
        float w = Ws[k][c];
#pragma unroll
        for (int r = 0; r < 16; r++) acc[r] += Xs[rg*16 + r][k] * w;
    }

#pragma unroll
    for (int r = 0; r < 16; r++)
        out[(rowbase + rg*16 + r) * 64 + c] = acc[r];
}

// ---------------------------------------------------------------------------
extern "C" void kernel_launch(void* const* d_in, const int* in_sizes, int n_in,
                              void* d_out, int out_size) {
    const float* x    = (const float*)d_in[0];
    const float* enc  = (const float*)d_in[1];
    const int*   msk  = (const int*)  d_in[2];
    const float* Wkv  = (const float*)d_in[3];
    const float* bkv  = (const float*)d_in[4];
    const float* Wq   = (const float*)d_in[5];
    const float* bq   = (const float*)d_in[6];
    const float* Wp   = (const float*)d_in[7];
    const float* bp   = (const float*)d_in[8];
    float* out = (float*)d_out;

    kv_kernel<<<ROWS_TOTAL/64, 256>>>(enc, Wkv, bkv);
    q_kernel<<<ROWS_TOTAL/64, 256>>>(x, Wq, bq);
    attn_kernel<<<dim3(BB*NH, TT/128), 128>>>(msk);
    proj_kernel<<<ROWS_TOTAL/64, 256>>>(Wp, bp, out);
}

// round 2
// speedup vs baseline: 1.2248x; 1.2248x over previous
#include <cuda_runtime.h>

#define DM 64
#define NH 4
#define HD 16
#define BB 16
#define TT 1024
#define ROWS_TOTAL (BB*TT)

typedef unsigned long long u64;

__device__ float g_K[ROWS_TOTAL*DM];    // [b,h,t,16]
__device__ float g_V[ROWS_TOTAL*DM];    // [b,h,t,16]
__device__ float g_Q[ROWS_TOTAL*DM];    // [b,h,t,16]
__device__ float g_ctx[ROWS_TOTAL*DM];  // [b,t,64]

// ---- packed f32x2 helpers (PTX-only instructions on sm_103a) ----
__device__ __forceinline__ u64 pk2(float lo, float hi) {
    u64 d;
    asm("mov.b64 %0,{%1,%2};" : "=l"(d)
        : "r"(__float_as_uint(lo)), "r"(__float_as_uint(hi)));
    return d;
}
__device__ __forceinline__ void up2(u64 d, float& lo, float& hi) {
    unsigned a, b;
    asm("mov.b64 {%0,%1},%2;" : "=r"(a), "=r"(b) : "l"(d));
    lo = __uint_as_float(a); hi = __uint_as_float(b);
}
__device__ __forceinline__ u64 fma2(u64 a, u64 b, u64 c) {
    u64 d;
    asm("fma.rn.f32x2 %0,%1,%2,%3;" : "=l"(d) : "l"(a), "l"(b), "l"(c));
    return d;
}
__device__ __forceinline__ u64 mul2(u64 a, u64 b) {
    u64 d;
    asm("mul.rn.f32x2 %0,%1,%2;" : "=l"(d) : "l"(a), "l"(b));
    return d;
}
__device__ __forceinline__ float ex2a(float x) {
    float y;
    asm("ex2.approx.f32 %0,%1;" : "=f"(y) : "f"(x));
    return y;
}

// ---------------------------------------------------------------------------
// KV projection. 256 thr, 64 rows/block. thread = 1 col x 32 rows.
// k in steps of 4: one broadcast LDS.128 feeds 4 FFMAs per row.
// ---------------------------------------------------------------------------
__global__ void __launch_bounds__(256) kv_kernel(const float* __restrict__ enc,
                                                 const float* __restrict__ Wkv,
                                                 const float* __restrict__ bkv) {
    __shared__ float Xs[64][64];
    __shared__ float Ws[64][128];
    int rowbase = blockIdx.x * 64;

    for (int i = threadIdx.x; i < 64*128/4; i += 256)
        ((float4*)Ws)[i] = ((const float4*)Wkv)[i];
    for (int i = threadIdx.x; i < 64*64/4; i += 256)
        ((float4*)Xs)[i] = ((const float4*)enc)[rowbase*16 + i];
    __syncthreads();

    int c  = threadIdx.x & 127;
    int rg = threadIdx.x >> 7;   // 0 or 1
    float bias = bkv[c];
    float acc[32];
#pragma unroll
    for (int r = 0; r < 32; r++) acc[r] = bias;

#pragma unroll 4
    for (int k0 = 0; k0 < 64; k0 += 4) {
        float w0 = Ws[k0][c], w1 = Ws[k0+1][c], w2 = Ws[k0+2][c], w3 = Ws[k0+3][c];
#pragma unroll
        for (int r = 0; r < 32; r++) {
            float4 x = *(const float4*)&Xs[rg*32 + r][k0];
            acc[r] += x.x*w0 + x.y*w1 + x.z*w2 + x.w*w3;
        }
    }

    int h = (c >> 4) & 3;
    int d = c & 15;
    float* dst = (c < 64) ? g_K : g_V;
#pragma unroll
    for (int r = 0; r < 32; r++) {
        int row = rowbase + rg*32 + r;
        int b = row >> 10, t = row & 1023;
        dst[(((b << 2) | h) * 1024 + t) * 16 + d] = acc[r];
    }
}

// ---------------------------------------------------------------------------
// Q projection. 256 thr, 64 rows/block. thread = 1 col x 16 rows.
// ---------------------------------------------------------------------------
__global__ void __launch_bounds__(256) q_kernel(const float* __restrict__ x,
                                                const float* __restrict__ Wq,
                                                const float* __restrict__ bq) {
    __shared__ float Xs[64][64];
    __shared__ float Ws[64][64];
    int rowbase = blockIdx.x * 64;

    for (int i = threadIdx.x; i < 64*64/4; i += 256) {
        ((float4*)Ws)[i] = ((const float4*)Wq)[i];
        ((float4*)Xs)[i] = ((const float4*)x)[rowbase*16 + i];
    }
    __syncthreads();

    int c  = threadIdx.x & 63;
    int rg = threadIdx.x >> 6;   // 0..3
    float bias = bq[c];
    float acc[16];
#pragma unroll
    for (int r = 0; r < 16; r++) acc[r] = bias;

#pragma unroll 4
    for (int k0 = 0; k0 < 64; k0 += 4) {
        float w0 = Ws[k0][c], w1 = Ws[k0+1][c], w2 = Ws[k0+2][c], w3 = Ws[k0+3][c];
#pragma unroll
        for (int r = 0; r < 16; r++) {
            float4 x = *(const float4*)&Xs[rg*16 + r][k0];
            acc[r] += x.x*w0 + x.y*w1 + x.z*w2 + x.w*w3;
        }
    }

    int h = c >> 4;
    int d = c & 15;
#pragma unroll
    for (int r = 0; r < 16; r++) {
        int row = rowbase + rg*16 + r;
        int b = row >> 10, t = row & 1023;
        g_Q[(((b << 2) | h) * 1024 + t) * 16 + d] = acc[r];
    }
}

// ---------------------------------------------------------------------------
// Attention. grid(64 bh, 8), block 64. Each thread owns 2 q rows (r0, r0+64),
// sharing K/V smem reads between them. All inner math is packed f32x2.
// Q is pre-scaled by 0.25*log2(e); softmax runs in the exp2 domain (raw EX2).
// Mask bias is folded into the dot-product chain initializer.
// ---------------------------------------------------------------------------
__global__ void __launch_bounds__(64) attn_kernel(const int* __restrict__ mask) {
    __shared__ float Ks[128][16];
    __shared__ float Vs[128][16];
    __shared__ u64 mb2[128];

    const float SCALE = 0.25f * 1.4426950408889634f;   // 1/sqrt(16) * log2(e)

    int bh = blockIdx.x;
    int b  = bh >> 2;
    int h  = bh & 3;
    int tid = threadIdx.x;
    int r0 = blockIdx.y * 128 + tid;     // second row = r0 + 64

    const u64 SS = pk2(SCALE, SCALE);
    u64 qa[8], qb[8];
    {
        const ulonglong2* qp0 = (const ulonglong2*)(g_Q + (bh*1024 + r0) * 16);
        const ulonglong2* qp1 = (const ulonglong2*)(g_Q + (bh*1024 + r0 + 64) * 16);
#pragma unroll
        for (int j = 0; j < 4; j++) {
            ulonglong2 t0 = qp0[j]; qa[2*j] = mul2(t0.x, SS); qa[2*j+1] = mul2(t0.y, SS);
            ulonglong2 t1 = qp1[j]; qb[2*j] = mul2(t1.x, SS); qb[2*j+1] = mul2(t1.y, SS);
        }
    }

    float m0 = -1e30f, m1 = -1e30f, l0 = 0.0f, l1 = 0.0f;
    u64 acc0[8], acc1[8];
#pragma unroll
    for (int j = 0; j < 8; j++) { acc0[j] = 0ull; acc1[j] = 0ull; }

    for (int tile = 0; tile < 8; ++tile) {
        int kb = tile * 128;
#pragma unroll
        for (int s = 0; s < 2; s++) {
            int kk = tid + 64*s;
            const float4* kp = (const float4*)(g_K + (bh*1024 + kb + kk) * 16);
            const float4* vp = (const float4*)(g_V + (bh*1024 + kb + kk) * 16);
            float4* ksd = (float4*)Ks[kk];
            float4* vsd = (float4*)Vs[kk];
            ksd[0]=kp[0]; ksd[1]=kp[1]; ksd[2]=kp[2]; ksd[3]=kp[3];
            vsd[0]=vp[0]; vsd[1]=vp[1]; vsd[2]=vp[2]; vsd[3]=vp[3];
            mb2[kk] = pk2(mask[b*1024 + kb + kk] ? 0.0f : -1e30f, 0.0f);
        }
        __syncthreads();

#pragma unroll 1
        for (int c0 = 0; c0 < 128; c0 += 16) {
            float s0[16], s1[16];
#pragma unroll
            for (int i = 0; i < 16; i++) {
                const ulonglong2* kr = (const ulonglong2*)Ks[c0 + i];
                ulonglong2 k0 = kr[0], k1 = kr[1], k2 = kr[2], k3 = kr[3];
                u64 init = mb2[c0 + i];
                u64 e0 = fma2(qa[0], k0.x, init);
                e0 = fma2(qa[1], k0.y, e0); e0 = fma2(qa[2], k1.x, e0);
                e0 = fma2(qa[3], k1.y, e0); e0 = fma2(qa[4], k2.x, e0);
                e0 = fma2(qa[5], k2.y, e0); e0 = fma2(qa[6], k3.x, e0);
                e0 = fma2(qa[7], k3.y, e0);
                u64 e1 = fma2(qb[0], k0.x, init);
                e1 = fma2(qb[1], k0.y, e1); e1 = fma2(qb[2], k1.x, e1);
                e1 = fma2(qb[3], k1.y, e1); e1 = fma2(qb[4], k2.x, e1);
                e1 = fma2(qb[5], k2.y, e1); e1 = fma2(qb[6], k3.x, e1);
                e1 = fma2(qb[7], k3.y, e1);
                float lo, hi;
                up2(e0, lo, hi); s0[i] = lo + hi;
                up2(e1, lo, hi); s1[i] = lo + hi;
            }

            float c0m = s0[0], c1m = s1[0];
#pragma unroll
            for (int i = 1; i < 16; i++) { c0m = fmaxf(c0m, s0[i]); c1m = fmaxf(c1m, s1[i]); }
            float n0 = fmaxf(m0, c0m), n1 = fmaxf(m1, c1m);
            float f0 = ex2a(m0 - n0), f1 = ex2a(m1 - n1);
            l0 *= f0; l1 *= f1;
            u64 fd0 = pk2(f0, f0), fd1 = pk2(f1, f1);
#pragma unroll
            for (int j = 0; j < 8; j++) { acc0[j] = mul2(acc0[j], fd0); acc1[j] = mul2(acc1[j], fd1); }
            m0 = n0; m1 = n1;

#pragma unroll
            for (int i = 0; i < 16; i++) {
                const ulonglong2* vr = (const ulonglong2*)Vs[c0 + i];
                ulonglong2 v0 = vr[0], v1 = vr[1], v2 = vr[2], v3 = vr[3];
                float p0 = ex2a(s0[i] - n0);
                float p1 = ex2a(s1[i] - n1);
                l0 += p0; l1 += p1;
                u64 pd0 = pk2(p0, p0), pd1 = pk2(p1, p1);
                acc0[0] = fma2(pd0, v0.x, acc0[0]); acc0[1] = fma2(pd0, v0.y, acc0[1]);
                acc0[2] = fma2(pd0, v1.x, acc0[2]); acc0[3] = fma2(pd0, v1.y, acc0[3]);
                acc0[4] = fma2(pd0, v2.x, acc0[4]); acc0[5] = fma2(pd0, v2.y, acc0[5]);
                acc0[6] = fma2(pd0, v3.x, acc0[6]); acc0[7] = fma2(pd0, v3.y, acc0[7]);
                acc1[0] = fma2(pd1, v0.x, acc1[0]); acc1[1] = fma2(pd1, v0.y, acc1[1]);
                acc1[2] = fma2(pd1, v1.x, acc1[2]); acc1[3] = fma2(pd1, v1.y, acc1[3]);
                acc1[4] = fma2(pd1, v2.x, acc1[4]); acc1[5] = fma2(pd1, v2.y, acc1[5]);
                acc1[6] = fma2(pd1, v3.x, acc1[6]); acc1[7] = fma2(pd1, v3.y, acc1[7]);
            }
        }
        __syncthreads();
    }

    float inv0 = 1.0f / l0;
    float inv1 = 1.0f / l1;
    u64 iv0 = pk2(inv0, inv0), iv1 = pk2(inv1, inv1);
    u64* o0 = (u64*)(g_ctx + (b*1024 + r0) * 64 + h*16);
    u64* o1 = (u64*)(g_ctx + (b*1024 + r0 + 64) * 64 + h*16);
#pragma unroll
    for (int j = 0; j < 8; j++) {
        o0[j] = mul2(acc0[j], iv0);
        o1[j] = mul2(acc1[j], iv1);
    }
}

// ---------------------------------------------------------------------------
// Output projection. 256 thr, 64 rows/block. thread = 1 col x 16 rows.
// ---------------------------------------------------------------------------
__global__ void __launch_bounds__(256) proj_kernel(const float* __restrict__ Wp,
                                                   const float* __restrict__ bp,
                                                   float* __restrict__ out) {
    __shared__ float Xs[64][64];
    __shared__ float Ws[64][64];
    int rowbase = blockIdx.x * 64;

    for (int i = threadIdx.x; i < 64*64/4; i += 256) {
        ((float4*)Ws)[i] = ((const float4*)Wp)[i];
        ((float4*)Xs)[i] = ((const float4*)g_ctx)[rowbase*16 + i];
    }
    __syncthreads();

    int c  = threadIdx.x & 63;
    int rg = threadIdx.x >> 6;
    float bias = bp[c];
    float acc[16];
#pragma unroll
    for (int r = 0; r < 16; r++) acc[r] = bias;

#pragma unroll 4
    for (int k0 = 0; k0 < 64; k0 += 4) {
        float w0 = Ws[k0][c], w1 = Ws[k0+1][c], w2 = Ws[k0+2][c], w3 = Ws[k0+3][c];
#pragma unroll
        for (int r = 0; r < 16; r++) {
            float4 x = *(const float4*)&Xs[rg*16 + r][k0];
            acc[r] += x.x*w0 + x.y*w1 + x.z*w2 + x.w*w3;
        }
    }

#pragma unroll
    for (int r = 0; r < 16; r++)
        out[(rowbase + rg*16 + r) * 64 + c] = acc[r];
}

// ---------------------------------------------------------------------------
extern "C" void kernel_launch(void* const* d_in, const int* in_sizes, int n_in,
                              void* d_out, int out_size) {
    const float* x    = (const float*)d_in[0];
    const float* enc  = (const float*)d_in[1];
    const int*   msk  = (const int*)  d_in[2];
    const float* Wkv  = (const float*)d_in[3];
    const float* bkv  = (const float*)d_in[4];
    const float* Wq   = (const float*)d_in[5];
    const float* bq   = (const float*)d_in[6];
    const float* Wp   = (const float*)d_in[7];
    const float* bp   = (const float*)d_in[8];
    float* out = (float*)d_out;

    kv_kernel<<<ROWS_TOTAL/64, 256>>>(enc, Wkv, bkv);
    q_kernel<<<ROWS_TOTAL/64, 256>>>(x, Wq, bq);
    attn_kernel<<<dim3(BB*NH, TT/128), 64>>>(msk);
    proj_kernel<<<ROWS_TOTAL/64, 256>>>(Wp, bp, out);
}